// round 15
// baseline (speedup 1.0000x reference)
#include <cuda_runtime.h>
#include <cuda_fp16.h>
#include <cstdint>
#include <math_constants.h>

#define Bq   8
#define Nq   8192
#define Sq   2048
#define Cin  512
#define NTt  128          // n-tile per CTA
#define MTt  128          // o-tile per CTA
#define KC   32           // k chunk
#define NCH  (Cin / KC)   // 16
#define NSLOT 512         // grid.x(64) * B(8)
#define Pq   (Bq * Nq)

// SMEM: 3 stages x [A 8K | B 8K] = 49152.
// Epilogue overlays: tile[128][132] (67584) + redS/redQ (8K) -> SMEM_TOT 75776.
#define STG      16384
#define B_OFF    8192
#define SMEM_TOT 75776

// ---------------- scratch (device globals) ----------------------------------
__device__ __align__(16) __half g_Xh[(size_t)Bq * Nq * Cin];     // fp16 acts
__device__ __align__(16) float  g_Y [(size_t)Bq * Nq * Cin];     // fp32 raw out
__device__ __align__(16) __half g_Wh[655360];    // w0(256K) w1(256K) w2(128K)
__device__ __align__(16) float g_p2t[(size_t)Bq * Sq * 256];
__device__ int   g_idx3[(size_t)Bq * Nq * 3];
__device__ float g_w3  [(size_t)Bq * Nq * 3];
__device__ float g_psum[512 * NSLOT];
__device__ float g_psq [512 * NSLOT];
__device__ __align__(16) float2 g_affine[3 * 512];   // (scale, shift)

// ---------------- helpers ----------------------------------------------------
__device__ __forceinline__ uint32_t smem_u32(const void* p) {
    uint32_t a;
    asm("{ .reg .u64 t; cvta.to.shared.u64 t, %1; cvt.u32.u64 %0, t; }"
        : "=r"(a) : "l"(p));
    return a;
}
#define SW64(off) ((off) ^ (((off) >> 3) & 0x30))
#define CP_ASYNC16(dst, src) \
    asm volatile("cp.async.cg.shared.global [%0], [%1], 16;" \
                 :: "r"(dst), "l"(src) : "memory")
#define CP_COMMIT()  asm volatile("cp.async.commit_group;" ::: "memory")
#define CP_WAIT(n)   asm volatile("cp.async.wait_group %0;" :: "n"(n) : "memory")

__device__ __forceinline__ void ldsm4(uint32_t* r, uint32_t addr) {
    asm volatile("ldmatrix.sync.aligned.m8n8.x4.shared.b16 {%0,%1,%2,%3}, [%4];"
                 : "=r"(r[0]), "=r"(r[1]), "=r"(r[2]), "=r"(r[3]) : "r"(addr));
}
__device__ __forceinline__ void mma16816(float* d, const uint32_t* a, const uint32_t* b) {
    asm volatile("mma.sync.aligned.m16n8k16.row.col.f32.f16.f16.f32 "
                 "{%0,%1,%2,%3}, {%4,%5,%6,%7}, {%8,%9}, {%0,%1,%2,%3};"
                 : "+f"(d[0]), "+f"(d[1]), "+f"(d[2]), "+f"(d[3])
                 : "r"(a[0]), "r"(a[1]), "r"(a[2]), "r"(a[3]),
                   "r"(b[0]), "r"(b[1]));
}
__device__ __forceinline__ float4 ldcs4(const float* p) {
    float4 v;
    asm volatile("ld.global.cs.v4.f32 {%0,%1,%2,%3}, [%4];"
                 : "=f"(v.x), "=f"(v.y), "=f"(v.z), "=f"(v.w) : "l"(p));
    return v;
}

// ---------------- transpose points2: [B,D2,S] -> [B,S,D2] -------------------
__global__ void transpose_p2(const float* __restrict__ p2) {
    __shared__ float t[32][33];
    int b  = blockIdx.z;
    int s0 = blockIdx.x * 32;
    int d0 = blockIdx.y * 32;
    int tx = threadIdx.x, ty = threadIdx.y;
    const float* src = p2 + (size_t)b * 256 * Sq;
    float*       dst = g_p2t + (size_t)b * Sq * 256;
#pragma unroll
    for (int i = 0; i < 4; i++)
        t[ty + i * 8][tx] = src[(size_t)(d0 + ty + i * 8) * Sq + s0 + tx];
    __syncthreads();
#pragma unroll
    for (int i = 0; i < 4; i++)
        dst[(size_t)(s0 + ty + i * 8) * 256 + d0 + tx] = t[tx][ty + i * 8];
}

// ---------------- 3-NN + inverse-distance weights (R10 version) --------------
__global__ void knn3_kernel(const float* __restrict__ xyz1, const float* __restrict__ xyz2) {
    __shared__ float4 sp[Sq];
    int b   = blockIdx.y;
    int tid = threadIdx.x;
    const float* x2 = xyz2 + (size_t)b * 3 * Sq;
    for (int s = tid; s < Sq; s += 128) {
        float X = x2[s], Y = x2[Sq + s], Z = x2[2 * Sq + s];
        sp[s] = make_float4(X, Y, Z, X * X + Y * Y + Z * Z);
    }
    __syncthreads();
    int n = blockIdx.x * 128 + tid;
    const float* x1 = xyz1 + (size_t)b * 3 * Nq;
    float px = x1[n], py = x1[Nq + n], pz = x1[2 * Nq + n];
    float pn = px * px + py * py + pz * pz;
    float d1 = CUDART_INF_F, d2 = CUDART_INF_F, d3 = CUDART_INF_F;
    int   i1 = 0, i2 = 0, i3 = 0;
    for (int s = 0; s < Sq; s++) {
        float4 c = sp[s];
        float dot = px * c.x + py * c.y + pz * c.z;
        float d   = pn + c.w - 2.0f * dot;
        if (d < d3) {
            if (d < d2) {
                if (d < d1) { d3 = d2; i3 = i2; d2 = d1; i2 = i1; d1 = d; i1 = s; }
                else        { d3 = d2; i3 = i2; d2 = d;  i2 = s; }
            } else          { d3 = d;  i3 = s; }
        }
    }
    float r1 = 1.0f / (d1 + 1e-8f);
    float r2 = 1.0f / (d2 + 1e-8f);
    float r3 = 1.0f / (d3 + 1e-8f);
    float rs = r1 + r2 + r3;
    size_t base = ((size_t)b * Nq + n) * 3;
    g_idx3[base] = i1; g_idx3[base + 1] = i2; g_idx3[base + 2] = i3;
    g_w3[base] = r1 / rs; g_w3[base + 1] = r2 / rs; g_w3[base + 2] = r3 / rs;
}

// ---------------- interpolate + concat -> fp16 [B,N,512] ---------------------
__global__ void interp_concat(const float* __restrict__ p1) {
    __shared__ float t[32][33];
    int b   = blockIdx.y;
    int n0  = blockIdx.x * 32;
    int tid = threadIdx.x;
    int tx  = tid & 31, ty = tid >> 5;
    const float* p1b = p1 + (size_t)b * 256 * Nq;
    __half* xo = g_Xh + (size_t)b * Nq * Cin;

    for (int ct = 0; ct < 8; ct++) {
        int c0 = ct * 32;
#pragma unroll
        for (int i = 0; i < 4; i++)
            t[ty + 8 * i][tx] = p1b[(size_t)(c0 + ty + 8 * i) * Nq + n0 + tx];
        __syncthreads();
#pragma unroll
        for (int i = 0; i < 4; i++) {
            int n = n0 + ty + 8 * i;
            xo[(size_t)n * Cin + c0 + tx] = __float2half_rn(t[tx][ty + 8 * i]);
        }
        __syncthreads();
    }

    const float* p2tb = g_p2t + (size_t)b * Sq * 256;
    const int lane = tid & 31;
    const int pt   = tid >> 5;           // 0..7
#pragma unroll
    for (int it = 0; it < 4; it++) {
        int nn = it * 8 + pt;
        size_t base = ((size_t)b * Nq + n0 + nn) * 3;
        int   j0 = g_idx3[base], j1 = g_idx3[base + 1], j2 = g_idx3[base + 2];
        float w0 = g_w3[base], w1 = g_w3[base + 1], w2 = g_w3[base + 2];
        const float* r0 = p2tb + (size_t)j0 * 256 + lane * 8;
        const float* r1 = p2tb + (size_t)j1 * 256 + lane * 8;
        const float* r2 = p2tb + (size_t)j2 * 256 + lane * 8;
        float4 a0 = *(const float4*)r0,       a1 = *(const float4*)(r0 + 4);
        float4 b0 = *(const float4*)r1,       b1 = *(const float4*)(r1 + 4);
        float4 c0 = *(const float4*)r2,       c1 = *(const float4*)(r2 + 4);
        float v0 = w0 * a0.x + w1 * b0.x + w2 * c0.x;
        float v1 = w0 * a0.y + w1 * b0.y + w2 * c0.y;
        float v2 = w0 * a0.z + w1 * b0.z + w2 * c0.z;
        float v3 = w0 * a0.w + w1 * b0.w + w2 * c0.w;
        float v4 = w0 * a1.x + w1 * b1.x + w2 * c1.x;
        float v5 = w0 * a1.y + w1 * b1.y + w2 * c1.y;
        float v6 = w0 * a1.z + w1 * b1.z + w2 * c1.z;
        float v7 = w0 * a1.w + w1 * b1.w + w2 * c1.w;
        __half2 h[4];
        h[0] = __floats2half2_rn(v0, v1);
        h[1] = __floats2half2_rn(v2, v3);
        h[2] = __floats2half2_rn(v4, v5);
        h[3] = __floats2half2_rn(v6, v7);
        *(uint2*)(xo + (size_t)(n0 + nn) * Cin + 256 + lane * 8)     = *(uint2*)&h[0];
        *(uint2*)(xo + (size_t)(n0 + nn) * Cin + 256 + lane * 8 + 4) = *(uint2*)&h[2];
    }
}

// ---------------- all-weights fp32 -> fp16 (single launch) -------------------
__global__ void wconv_all(const float* __restrict__ w0, const float* __restrict__ w1,
                          const float* __restrict__ w2) {
    int i = blockIdx.x * 256 + threadIdx.x;
    if (i >= 655360) return;
    float v;
    if (i < 262144)       v = w0[i];
    else if (i < 524288)  v = w1[i - 262144];
    else                  v = w2[i - 524288];
    g_Wh[i] = __float2half_rn(v);
}

// ---------------- fp16 GEMM, 128x128 CTA / 64x32 warptile, occ 2 (R10) -------
__global__ __launch_bounds__(256, 2)
void gemm_mma(const __half* __restrict__ Wh, const __half* __restrict__ Xh,
              float* __restrict__ Y, int O) {
    extern __shared__ char smem[];
    const int tid  = threadIdx.x;
    const int wid  = tid >> 5;
    const int lane = tid & 31;
    const int b     = blockIdx.z;
    const int nBase = blockIdx.x * NTt;
    const int oBase = blockIdx.y * MTt;
    const uint32_t sb = smem_u32(smem);
    const __half* Xb = Xh + (size_t)b * Nq * Cin;

    const int wm0 = (wid >> 2) * 64;   // o
    const int wn0 = (wid & 3) * 32;    // n

    float acc[16][4];
#pragma unroll
    for (int i = 0; i < 16; i++)
#pragma unroll
        for (int j = 0; j < 4; j++) acc[i][j] = 0.0f;

    auto load_chunk = [&](int kt, int s) {
        uint32_t st = sb + s * STG;
#pragma unroll
        for (int i = 0; i < 2; i++) {
            int idx = tid + i * 256;
            int row = idx >> 2, c = idx & 3;
            uint32_t sw = SW64((uint32_t)(row * 64 + c * 16));
            CP_ASYNC16(st + sw, Wh + (size_t)(oBase + row) * Cin + kt + c * 8);
            CP_ASYNC16(st + B_OFF + sw,
                       Xb + (size_t)(nBase + row) * Cin + kt + c * 8);
        }
    };

    const int q  = lane >> 3, lr = lane & 7;
    const int a_row_off  = (q & 1) * 8 + lr;   // A x4: m16 x k16 (4 tiles)
    const int a_col_byte = (q >> 1) * 16;
    const int b_row_off  = (q >> 1) * 8 + lr;  // B x4: t0/t1 = n tile, t2/t3 = n+8
    const int b_col_byte = (q & 1) * 16;

    load_chunk(0, 0);  CP_COMMIT();
    load_chunk(KC, 1); CP_COMMIT();

    for (int k = 0; k < NCH; k++) {
        if (k < NCH - 1) { CP_WAIT(1); } else { CP_WAIT(0); }
        __syncthreads();
        if (k + 2 < NCH) {
            load_chunk((k + 2) * KC, (k + 2) % 3);
            CP_COMMIT();
        }
        const int s = k % 3;
        uint32_t aAd = sb + s * STG;
        uint32_t bAd = aAd + B_OFF;

#pragma unroll
        for (int kk = 0; kk < KC; kk += 16) {
            uint32_t af[4][4];
#pragma unroll
            for (int mi = 0; mi < 4; mi++) {
                int row = wm0 + mi * 16 + a_row_off;
                uint32_t sw = SW64((uint32_t)(row * 64 + kk * 2 + a_col_byte));
                ldsm4(af[mi], aAd + sw);
            }
#pragma unroll
            for (int nj = 0; nj < 2; nj++) {         // n-tile pair (2nj, 2nj+1)
                int row = wn0 + nj * 16 + b_row_off;
                uint32_t sw = SW64((uint32_t)(row * 64 + kk * 2 + b_col_byte));
                uint32_t bf[4];                       // r0,r1: n tile; r2,r3: n+8
                ldsm4(bf, bAd + sw);
#pragma unroll
                for (int mi = 0; mi < 4; mi++) {
                    mma16816(acc[mi * 4 + 2 * nj],     af[mi], bf);
                    mma16816(acc[mi * 4 + 2 * nj + 1], af[mi], bf + 2);
                }
            }
        }
    }
    __syncthreads();   // protect smem reuse below

    // ---- epilogue: stage tile through SMEM, coalesced store + BN partials ----
    float* tile = (float*)smem;                    // [128][132] = 67584 B
    float* redS = (float*)(smem + 67584);          // [8][128]
    float* redQ = (float*)(smem + 71680);          // [8][128]

    const int o_thr = lane >> 2;
    const int n_thr = 2 * (lane & 3);
#pragma unroll
    for (int mi = 0; mi < 4; mi++) {
#pragma unroll
        for (int ni = 0; ni < 4; ni++) {
            int o0 = wm0 + mi * 16 + o_thr;
            int n0 = wn0 + ni * 8 + n_thr;
            float* d = acc[mi * 4 + ni];
            tile[n0 * 132 + o0]           = d[0];
            tile[(n0 + 1) * 132 + o0]     = d[1];
            tile[n0 * 132 + o0 + 8]       = d[2];
            tile[(n0 + 1) * 132 + o0 + 8] = d[3];
        }
    }
    __syncthreads();

    const int jrow = tid >> 5;
    const int o4   = (tid & 31) * 4;
    float s0 = 0, s1 = 0, s2 = 0, s3 = 0;
    float q0 = 0, q1 = 0, q2 = 0, q3 = 0;
#pragma unroll
    for (int i = 0; i < 16; i++) {
        int n = jrow + i * 8;
        float4 v = *(const float4*)&tile[n * 132 + o4];
        *(float4*)&Y[((size_t)b * Nq + nBase + n) * O + oBase + o4] = v;
        s0 += v.x; s1 += v.y; s2 += v.z; s3 += v.w;
        q0 += v.x * v.x; q1 += v.y * v.y; q2 += v.z * v.z; q3 += v.w * v.w;
    }
    *(float4*)&redS[jrow * 128 + o4] = make_float4(s0, s1, s2, s3);
    *(float4*)&redQ[jrow * 128 + o4] = make_float4(q0, q1, q2, q3);
    __syncthreads();

    if (tid < 128) {
        float S = 0, Q = 0;
#pragma unroll
        for (int j = 0; j < 8; j++) {
            S += redS[j * 128 + tid];
            Q += redQ[j * 128 + tid];
        }
        int slot = b * gridDim.x + blockIdx.x;
        g_psum[(size_t)(oBase + tid) * NSLOT + slot] = S;
        g_psq [(size_t)(oBase + tid) * NSLOT + slot] = Q;
    }
}

// ---------------- BN finalize: one block per channel -------------------------
__global__ void bn_fin(const float* __restrict__ g, const float* __restrict__ beta,
                       int layer) {
    int o = blockIdx.x;
    int t = threadIdx.x;   // 256
    float s = g_psum[(size_t)o * NSLOT + t] + g_psum[(size_t)o * NSLOT + t + 256];
    float q = g_psq [(size_t)o * NSLOT + t] + g_psq [(size_t)o * NSLOT + t + 256];
    __shared__ float ss[8], qq[8];
#pragma unroll
    for (int off = 16; off; off >>= 1) {
        s += __shfl_down_sync(0xffffffffu, s, off);
        q += __shfl_down_sync(0xffffffffu, q, off);
    }
    if ((t & 31) == 0) { ss[t >> 5] = s; qq[t >> 5] = q; }
    __syncthreads();
    if (t == 0) {
        float S = 0, Q = 0;
#pragma unroll
        for (int j = 0; j < 8; j++) { S += ss[j]; Q += qq[j]; }
        const float invP = 1.0f / (float)Pq;
        float mean = S * invP;
        float var  = Q * invP - mean * mean;
        float rstd = rsqrtf(var + 1e-5f);
        float a    = g[o] * rstd;
        g_affine[layer * 512 + o] = make_float2(a, beta[o] - mean * a);
    }
}

// ---------------- BN+ReLU + fp16 convert: Y [B,N,512] -> g_Xh ---------------
// 8 floats per thread, streaming (evict-first) loads of single-use Y.
__global__ void act_convert(const float* __restrict__ y, const float2* __restrict__ aff) {
    size_t i8 = (size_t)blockIdx.x * 256 + threadIdx.x;   // 8-float index
    const float* yp = y + i8 * 8;
    float4 v0 = ldcs4(yp);
    float4 v1 = ldcs4(yp + 4);
    int o = (int)((i8 * 8) & (Cin - 1));
    const float2* ap = aff + o;
    float2 p0 = ap[0], p1 = ap[1], p2 = ap[2], p3 = ap[3];
    float2 p4 = ap[4], p5 = ap[5], p6 = ap[6], p7 = ap[7];
    float x0 = fmaxf(fmaf(p0.x, v0.x, p0.y), 0.0f);
    float x1 = fmaxf(fmaf(p1.x, v0.y, p1.y), 0.0f);
    float x2 = fmaxf(fmaf(p2.x, v0.z, p2.y), 0.0f);
    float x3 = fmaxf(fmaf(p3.x, v0.w, p3.y), 0.0f);
    float x4 = fmaxf(fmaf(p4.x, v1.x, p4.y), 0.0f);
    float x5 = fmaxf(fmaf(p5.x, v1.y, p5.y), 0.0f);
    float x6 = fmaxf(fmaf(p6.x, v1.z, p6.y), 0.0f);
    float x7 = fmaxf(fmaf(p7.x, v1.w, p7.y), 0.0f);
    __half2 h[4];
    h[0] = __floats2half2_rn(x0, x1);
    h[1] = __floats2half2_rn(x2, x3);
    h[2] = __floats2half2_rn(x4, x5);
    h[3] = __floats2half2_rn(x6, x7);
    *(uint4*)(g_Xh + i8 * 8) = *(uint4*)h;
}

// ---------------- final BN+ReLU + transpose to [B,256,N] ---------------------
__global__ void final_out(const float* __restrict__ y, float* __restrict__ out) {
    __shared__ float t[32][33];
    int b = blockIdx.z, n0 = blockIdx.x * 32, c0 = blockIdx.y * 32;
    int tx = threadIdx.x, ty = threadIdx.y;
    const float* yb = y + (size_t)b * Nq * 256;
    float2 ad = g_affine[2 * 512 + c0 + tx];
#pragma unroll
    for (int i = 0; i < 4; i++) {
        int n = n0 + ty + 8 * i;
        float v = __ldcs(&yb[(size_t)n * 256 + c0 + tx]);
        t[ty + 8 * i][tx] = fmaxf(fmaf(ad.x, v, ad.y), 0.0f);
    }
    __syncthreads();
#pragma unroll
    for (int i = 0; i < 4; i++)
        out[((size_t)b * 256 + c0 + ty + 8 * i) * Nq + n0 + tx] = t[tx][ty + 8 * i];
}

// ---------------- launch -----------------------------------------------------
extern "C" void kernel_launch(void* const* d_in, const int* in_sizes, int n_in,
                              void* d_out, int out_size) {
    const float* xyz1    = (const float*)d_in[0];
    const float* xyz2    = (const float*)d_in[1];
    const float* points1 = (const float*)d_in[2];
    const float* points2 = (const float*)d_in[3];
    const float* w0  = (const float*)d_in[4];
    const float* g0  = (const float*)d_in[6];
    const float* be0 = (const float*)d_in[7];
    const float* w1  = (const float*)d_in[8];
    const float* g1  = (const float*)d_in[10];
    const float* be1 = (const float*)d_in[11];
    const float* w2  = (const float*)d_in[12];
    const float* g2  = (const float*)d_in[14];
    const float* be2 = (const float*)d_in[15];
    float* out = (float*)d_out;

    __half *Wh, *Xh;
    float *Y;
    float2* affine;
    cudaGetSymbolAddress((void**)&Wh, g_Wh);
    cudaGetSymbolAddress((void**)&Xh, g_Xh);
    cudaGetSymbolAddress((void**)&Y, g_Y);
    cudaGetSymbolAddress((void**)&affine, g_affine);

    cudaFuncSetAttribute(gemm_mma, cudaFuncAttributeMaxDynamicSharedMemorySize, SMEM_TOT);

    // all weights -> fp16 in one launch
    wconv_all<<<(655360 + 255) / 256, 256>>>(w0, w1, w2);

    // geometry + interpolation + concat (fp16 [B,N,512] into g_Xh)
    transpose_p2<<<dim3(Sq / 32, 256 / 32, Bq), dim3(32, 8)>>>(points2);
    knn3_kernel<<<dim3(Nq / 128, Bq), 128>>>(xyz1, xyz2);
    interp_concat<<<dim3(Nq / 32, Bq), 256>>>(points1);

    // layer 0
    gemm_mma<<<dim3(Nq / NTt, 512 / MTt, Bq), 256, SMEM_TOT>>>(Wh, Xh, Y, 512);
    bn_fin<<<512, 256>>>(g0, be0, 0);
    act_convert<<<(Bq * Nq * Cin / 8) / 256, 256>>>(Y, affine);
    // layer 1
    gemm_mma<<<dim3(Nq / NTt, 512 / MTt, Bq), 256, SMEM_TOT>>>(Wh + 262144, Xh, Y, 512);
    bn_fin<<<512, 256>>>(g1, be1, 1);
    act_convert<<<(Bq * Nq * Cin / 8) / 256, 256>>>(Y, affine + 512);
    // layer 2
    gemm_mma<<<dim3(Nq / NTt, 256 / MTt, Bq), 256, SMEM_TOT>>>(Wh + 524288, Xh, Y, 256);
    bn_fin<<<256, 256>>>(g2, be2, 2);
    final_out<<<dim3(Nq / 32, 8, Bq), dim3(32, 8)>>>(Y, out);
}

// round 16
// speedup vs baseline: 1.1046x; 1.1046x over previous
#include <cuda_runtime.h>
#include <cuda_fp16.h>
#include <cstdint>
#include <math_constants.h>

#define Bq   8
#define Nq   8192
#define Sq   2048
#define Cin  512
#define NTt  128          // n-tile per CTA
#define MTt  128          // o-tile per CTA
#define KC   32           // k chunk
#define NCH  (Cin / KC)   // 16
#define NSLOT 512         // grid.x(64) * B(8)
#define Pq   (Bq * Nq)

// SMEM: 3 stages x [A 8K | B 8K] = 49152.
// Epilogue overlays: tile[128][132] (67584) + redS/redQ (8K) -> SMEM_TOT 75776.
#define STG      16384
#define B_OFF    8192
#define SMEM_TOT 75776

// ---------------- scratch (device globals) ----------------------------------
__device__ __align__(16) __half g_Xh[(size_t)Bq * Nq * Cin];     // fp16 acts
__device__ __align__(16) float  g_Y [(size_t)Bq * Nq * Cin];     // fp32 raw out
__device__ __align__(16) __half g_Wh[655360];    // w0(256K) w1(256K) w2(128K)
__device__ __align__(16) float g_p2t[(size_t)Bq * Sq * 256];
__device__ int   g_idx3[(size_t)Bq * Nq * 3];
__device__ float g_w3  [(size_t)Bq * Nq * 3];
__device__ float g_psum[512 * NSLOT];
__device__ float g_psq [512 * NSLOT];
__device__ __align__(16) float2 g_affine[3 * 512];   // (scale, shift)

// ---------------- helpers ----------------------------------------------------
__device__ __forceinline__ uint32_t smem_u32(const void* p) {
    uint32_t a;
    asm("{ .reg .u64 t; cvta.to.shared.u64 t, %1; cvt.u32.u64 %0, t; }"
        : "=r"(a) : "l"(p));
    return a;
}
#define SW64(off) ((off) ^ (((off) >> 3) & 0x30))
#define CP_ASYNC16(dst, src) \
    asm volatile("cp.async.cg.shared.global [%0], [%1], 16;" \
                 :: "r"(dst), "l"(src) : "memory")
#define CP_COMMIT()  asm volatile("cp.async.commit_group;" ::: "memory")
#define CP_WAIT(n)   asm volatile("cp.async.wait_group %0;" :: "n"(n) : "memory")

__device__ __forceinline__ void ldsm4(uint32_t* r, uint32_t addr) {
    asm volatile("ldmatrix.sync.aligned.m8n8.x4.shared.b16 {%0,%1,%2,%3}, [%4];"
                 : "=r"(r[0]), "=r"(r[1]), "=r"(r[2]), "=r"(r[3]) : "r"(addr));
}
__device__ __forceinline__ void mma16816(float* d, const uint32_t* a, const uint32_t* b) {
    asm volatile("mma.sync.aligned.m16n8k16.row.col.f32.f16.f16.f32 "
                 "{%0,%1,%2,%3}, {%4,%5,%6,%7}, {%8,%9}, {%0,%1,%2,%3};"
                 : "+f"(d[0]), "+f"(d[1]), "+f"(d[2]), "+f"(d[3])
                 : "r"(a[0]), "r"(a[1]), "r"(a[2]), "r"(a[3]),
                   "r"(b[0]), "r"(b[1]));
}

// ---------------- transpose points2: [B,D2,S] -> [B,S,D2] -------------------
__global__ void transpose_p2(const float* __restrict__ p2) {
    __shared__ float t[32][33];
    int b  = blockIdx.z;
    int s0 = blockIdx.x * 32;
    int d0 = blockIdx.y * 32;
    int tx = threadIdx.x, ty = threadIdx.y;
    const float* src = p2 + (size_t)b * 256 * Sq;
    float*       dst = g_p2t + (size_t)b * Sq * 256;
#pragma unroll
    for (int i = 0; i < 4; i++)
        t[ty + i * 8][tx] = src[(size_t)(d0 + ty + i * 8) * Sq + s0 + tx];
    __syncthreads();
#pragma unroll
    for (int i = 0; i < 4; i++)
        dst[(size_t)(s0 + ty + i * 8) * 256 + d0 + tx] = t[tx][ty + i * 8];
}

// ---------------- 3-NN + inverse-distance weights ----------------------------
__global__ void knn3_kernel(const float* __restrict__ xyz1, const float* __restrict__ xyz2) {
    __shared__ float4 sp[Sq];
    int b   = blockIdx.y;
    int tid = threadIdx.x;
    const float* x2 = xyz2 + (size_t)b * 3 * Sq;
    for (int s = tid; s < Sq; s += 128) {
        float X = x2[s], Y = x2[Sq + s], Z = x2[2 * Sq + s];
        sp[s] = make_float4(X, Y, Z, X * X + Y * Y + Z * Z);
    }
    __syncthreads();
    int n = blockIdx.x * 128 + tid;
    const float* x1 = xyz1 + (size_t)b * 3 * Nq;
    float px = x1[n], py = x1[Nq + n], pz = x1[2 * Nq + n];
    float pn = px * px + py * py + pz * pz;
    float d1 = CUDART_INF_F, d2 = CUDART_INF_F, d3 = CUDART_INF_F;
    int   i1 = 0, i2 = 0, i3 = 0;
    for (int s = 0; s < Sq; s++) {
        float4 c = sp[s];
        float dot = px * c.x + py * c.y + pz * c.z;
        float d   = pn + c.w - 2.0f * dot;
        if (d < d3) {
            if (d < d2) {
                if (d < d1) { d3 = d2; i3 = i2; d2 = d1; i2 = i1; d1 = d; i1 = s; }
                else        { d3 = d2; i3 = i2; d2 = d;  i2 = s; }
            } else          { d3 = d;  i3 = s; }
        }
    }
    float r1 = 1.0f / (d1 + 1e-8f);
    float r2 = 1.0f / (d2 + 1e-8f);
    float r3 = 1.0f / (d3 + 1e-8f);
    float rs = r1 + r2 + r3;
    size_t base = ((size_t)b * Nq + n) * 3;
    g_idx3[base] = i1; g_idx3[base + 1] = i2; g_idx3[base + 2] = i3;
    g_w3[base] = r1 / rs; g_w3[base + 1] = r2 / rs; g_w3[base + 2] = r3 / rs;
}

// ---------------- interpolate + concat -> fp16 [B,N,512] ---------------------
__global__ void interp_concat(const float* __restrict__ p1) {
    __shared__ float t[32][33];
    int b   = blockIdx.y;
    int n0  = blockIdx.x * 32;
    int tid = threadIdx.x;
    int tx  = tid & 31, ty = tid >> 5;
    const float* p1b = p1 + (size_t)b * 256 * Nq;
    __half* xo = g_Xh + (size_t)b * Nq * Cin;

    for (int ct = 0; ct < 8; ct++) {
        int c0 = ct * 32;
#pragma unroll
        for (int i = 0; i < 4; i++)
            t[ty + 8 * i][tx] = p1b[(size_t)(c0 + ty + 8 * i) * Nq + n0 + tx];
        __syncthreads();
#pragma unroll
        for (int i = 0; i < 4; i++) {
            int n = n0 + ty + 8 * i;
            xo[(size_t)n * Cin + c0 + tx] = __float2half_rn(t[tx][ty + 8 * i]);
        }
        __syncthreads();
    }

    const float* p2tb = g_p2t + (size_t)b * Sq * 256;
    const int lane = tid & 31;
    const int pt   = tid >> 5;           // 0..7
#pragma unroll
    for (int it = 0; it < 4; it++) {
        int nn = it * 8 + pt;
        size_t base = ((size_t)b * Nq + n0 + nn) * 3;
        int   j0 = g_idx3[base], j1 = g_idx3[base + 1], j2 = g_idx3[base + 2];
        float w0 = g_w3[base], w1 = g_w3[base + 1], w2 = g_w3[base + 2];
        const float* r0 = p2tb + (size_t)j0 * 256 + lane * 8;
        const float* r1 = p2tb + (size_t)j1 * 256 + lane * 8;
        const float* r2 = p2tb + (size_t)j2 * 256 + lane * 8;
        float4 a0 = *(const float4*)r0,       a1 = *(const float4*)(r0 + 4);
        float4 b0 = *(const float4*)r1,       b1 = *(const float4*)(r1 + 4);
        float4 c0 = *(const float4*)r2,       c1 = *(const float4*)(r2 + 4);
        float v0 = w0 * a0.x + w1 * b0.x + w2 * c0.x;
        float v1 = w0 * a0.y + w1 * b0.y + w2 * c0.y;
        float v2 = w0 * a0.z + w1 * b0.z + w2 * c0.z;
        float v3 = w0 * a0.w + w1 * b0.w + w2 * c0.w;
        float v4 = w0 * a1.x + w1 * b1.x + w2 * c1.x;
        float v5 = w0 * a1.y + w1 * b1.y + w2 * c1.y;
        float v6 = w0 * a1.z + w1 * b1.z + w2 * c1.z;
        float v7 = w0 * a1.w + w1 * b1.w + w2 * c1.w;
        __half2 h[4];
        h[0] = __floats2half2_rn(v0, v1);
        h[1] = __floats2half2_rn(v2, v3);
        h[2] = __floats2half2_rn(v4, v5);
        h[3] = __floats2half2_rn(v6, v7);
        *(uint2*)(xo + (size_t)(n0 + nn) * Cin + 256 + lane * 8)     = *(uint2*)&h[0];
        *(uint2*)(xo + (size_t)(n0 + nn) * Cin + 256 + lane * 8 + 4) = *(uint2*)&h[2];
    }
}

// ---------------- all-weights fp32 -> fp16 (single launch) -------------------
__global__ void wconv_all(const float* __restrict__ w0, const float* __restrict__ w1,
                          const float* __restrict__ w2) {
    int i = blockIdx.x * 256 + threadIdx.x;
    if (i >= 655360) return;
    float v;
    if (i < 262144)       v = w0[i];
    else if (i < 524288)  v = w1[i - 262144];
    else                  v = w2[i - 524288];
    g_Wh[i] = __float2half_rn(v);
}

// ---------------- fp16 GEMM, 128x128 CTA / 64x32 warptile, occ 2 -------------
__global__ __launch_bounds__(256, 2)
void gemm_mma(const __half* __restrict__ Wh, const __half* __restrict__ Xh,
              float* __restrict__ Y, int O) {
    extern __shared__ char smem[];
    const int tid  = threadIdx.x;
    const int wid  = tid >> 5;
    const int lane = tid & 31;
    const int b     = blockIdx.z;
    const int nBase = blockIdx.x * NTt;
    const int oBase = blockIdx.y * MTt;
    const uint32_t sb = smem_u32(smem);
    const __half* Xb = Xh + (size_t)b * Nq * Cin;

    const int wm0 = (wid >> 2) * 64;   // o
    const int wn0 = (wid & 3) * 32;    // n

    float acc[16][4];
#pragma unroll
    for (int i = 0; i < 16; i++)
#pragma unroll
        for (int j = 0; j < 4; j++) acc[i][j] = 0.0f;

    auto load_chunk = [&](int kt, int s) {
        uint32_t st = sb + s * STG;
#pragma unroll
        for (int i = 0; i < 2; i++) {
            int idx = tid + i * 256;
            int row = idx >> 2, c = idx & 3;
            uint32_t sw = SW64((uint32_t)(row * 64 + c * 16));
            CP_ASYNC16(st + sw, Wh + (size_t)(oBase + row) * Cin + kt + c * 8);
            CP_ASYNC16(st + B_OFF + sw,
                       Xb + (size_t)(nBase + row) * Cin + kt + c * 8);
        }
    };

    const int q  = lane >> 3, lr = lane & 7;
    const int a_row_off  = (q & 1) * 8 + lr;   // A x4: m16 x k16 (4 tiles)
    const int a_col_byte = (q >> 1) * 16;
    const int b_row_off  = (q >> 1) * 8 + lr;  // B x4: t0/t1 = n tile, t2/t3 = n+8
    const int b_col_byte = (q & 1) * 16;

    load_chunk(0, 0);  CP_COMMIT();
    load_chunk(KC, 1); CP_COMMIT();

    for (int k = 0; k < NCH; k++) {
        if (k < NCH - 1) { CP_WAIT(1); } else { CP_WAIT(0); }
        __syncthreads();
        if (k + 2 < NCH) {
            load_chunk((k + 2) * KC, (k + 2) % 3);
            CP_COMMIT();
        }
        const int s = k % 3;
        uint32_t aAd = sb + s * STG;
        uint32_t bAd = aAd + B_OFF;

#pragma unroll
        for (int kk = 0; kk < KC; kk += 16) {
            uint32_t af[4][4];
#pragma unroll
            for (int mi = 0; mi < 4; mi++) {
                int row = wm0 + mi * 16 + a_row_off;
                uint32_t sw = SW64((uint32_t)(row * 64 + kk * 2 + a_col_byte));
                ldsm4(af[mi], aAd + sw);
            }
#pragma unroll
            for (int nj = 0; nj < 2; nj++) {         // n-tile pair (2nj, 2nj+1)
                int row = wn0 + nj * 16 + b_row_off;
                uint32_t sw = SW64((uint32_t)(row * 64 + kk * 2 + b_col_byte));
                uint32_t bf[4];                       // r0,r1: n tile; r2,r3: n+8
                ldsm4(bf, bAd + sw);
#pragma unroll
                for (int mi = 0; mi < 4; mi++) {
                    mma16816(acc[mi * 4 + 2 * nj],     af[mi], bf);
                    mma16816(acc[mi * 4 + 2 * nj + 1], af[mi], bf + 2);
                }
            }
        }
    }
    __syncthreads();   // protect smem reuse below

    // ---- epilogue: stage tile through SMEM, coalesced store + BN partials ----
    float* tile = (float*)smem;                    // [128][132] = 67584 B
    float* redS = (float*)(smem + 67584);          // [8][128]
    float* redQ = (float*)(smem + 71680);          // [8][128]

    const int o_thr = lane >> 2;
    const int n_thr = 2 * (lane & 3);
#pragma unroll
    for (int mi = 0; mi < 4; mi++) {
#pragma unroll
        for (int ni = 0; ni < 4; ni++) {
            int o0 = wm0 + mi * 16 + o_thr;
            int n0 = wn0 + ni * 8 + n_thr;
            float* d = acc[mi * 4 + ni];
            tile[n0 * 132 + o0]           = d[0];
            tile[(n0 + 1) * 132 + o0]     = d[1];
            tile[n0 * 132 + o0 + 8]       = d[2];
            tile[(n0 + 1) * 132 + o0 + 8] = d[3];
        }
    }
    __syncthreads();

    const int jrow = tid >> 5;
    const int o4   = (tid & 31) * 4;
    float s0 = 0, s1 = 0, s2 = 0, s3 = 0;
    float q0 = 0, q1 = 0, q2 = 0, q3 = 0;
#pragma unroll
    for (int i = 0; i < 16; i++) {
        int n = jrow + i * 8;
        float4 v = *(const float4*)&tile[n * 132 + o4];
        *(float4*)&Y[((size_t)b * Nq + nBase + n) * O + oBase + o4] = v;
        s0 += v.x; s1 += v.y; s2 += v.z; s3 += v.w;
        q0 += v.x * v.x; q1 += v.y * v.y; q2 += v.z * v.z; q3 += v.w * v.w;
    }
    *(float4*)&redS[jrow * 128 + o4] = make_float4(s0, s1, s2, s3);
    *(float4*)&redQ[jrow * 128 + o4] = make_float4(q0, q1, q2, q3);
    __syncthreads();

    if (tid < 128) {
        float S = 0, Q = 0;
#pragma unroll
        for (int j = 0; j < 8; j++) {
            S += redS[j * 128 + tid];
            Q += redQ[j * 128 + tid];
        }
        int slot = b * gridDim.x + blockIdx.x;
        g_psum[(size_t)(oBase + tid) * NSLOT + slot] = S;
        g_psq [(size_t)(oBase + tid) * NSLOT + slot] = Q;
    }
}

// ---------------- BN finalize: one block per channel -------------------------
__global__ void bn_fin(const float* __restrict__ g, const float* __restrict__ beta,
                       int layer) {
    int o = blockIdx.x;
    int t = threadIdx.x;   // 256
    float s = g_psum[(size_t)o * NSLOT + t] + g_psum[(size_t)o * NSLOT + t + 256];
    float q = g_psq [(size_t)o * NSLOT + t] + g_psq [(size_t)o * NSLOT + t + 256];
    __shared__ float ss[8], qq[8];
#pragma unroll
    for (int off = 16; off; off >>= 1) {
        s += __shfl_down_sync(0xffffffffu, s, off);
        q += __shfl_down_sync(0xffffffffu, q, off);
    }
    if ((t & 31) == 0) { ss[t >> 5] = s; qq[t >> 5] = q; }
    __syncthreads();
    if (t == 0) {
        float S = 0, Q = 0;
#pragma unroll
        for (int j = 0; j < 8; j++) { S += ss[j]; Q += qq[j]; }
        const float invP = 1.0f / (float)Pq;
        float mean = S * invP;
        float var  = Q * invP - mean * mean;
        float rstd = rsqrtf(var + 1e-5f);
        float a    = g[o] * rstd;
        g_affine[layer * 512 + o] = make_float2(a, beta[o] - mean * a);
    }
}

// ---------------- BN+ReLU + fp16 convert: Y [B,N,512] -> g_Xh ---------------
__global__ void act_convert(const float* __restrict__ y, const float2* __restrict__ aff) {
    size_t i4 = (size_t)blockIdx.x * 256 + threadIdx.x;
    float4 v = ((const float4*)y)[i4];
    int o = (int)((i4 * 4) & (Cin - 1));
    float2 p0 = aff[o], p1 = aff[o + 1], p2 = aff[o + 2], p3 = aff[o + 3];
    float x0 = fmaxf(fmaf(p0.x, v.x, p0.y), 0.0f);
    float x1 = fmaxf(fmaf(p1.x, v.y, p1.y), 0.0f);
    float x2 = fmaxf(fmaf(p2.x, v.z, p2.y), 0.0f);
    float x3 = fmaxf(fmaf(p3.x, v.w, p3.y), 0.0f);
    ((__half2*)g_Xh)[2 * i4]     = __floats2half2_rn(x0, x1);
    ((__half2*)g_Xh)[2 * i4 + 1] = __floats2half2_rn(x2, x3);
}

// ---------------- final BN+ReLU + transpose to [B,256,N] ---------------------
__global__ void final_out(const float* __restrict__ y, float* __restrict__ out) {
    __shared__ float t[32][33];
    int b = blockIdx.z, n0 = blockIdx.x * 32, c0 = blockIdx.y * 32;
    int tx = threadIdx.x, ty = threadIdx.y;
    const float* yb = y + (size_t)b * Nq * 256;
    float2 ad = g_affine[2 * 512 + c0 + tx];
#pragma unroll
    for (int i = 0; i < 4; i++) {
        int n = n0 + ty + 8 * i;
        float v = yb[(size_t)n * 256 + c0 + tx];
        t[ty + 8 * i][tx] = fmaxf(fmaf(ad.x, v, ad.y), 0.0f);
    }
    __syncthreads();
#pragma unroll
    for (int i = 0; i < 4; i++)
        out[((size_t)b * 256 + c0 + ty + 8 * i) * Nq + n0 + tx] = t[tx][ty + 8 * i];
}

// ---------------- launch -----------------------------------------------------
extern "C" void kernel_launch(void* const* d_in, const int* in_sizes, int n_in,
                              void* d_out, int out_size) {
    const float* xyz1    = (const float*)d_in[0];
    const float* xyz2    = (const float*)d_in[1];
    const float* points1 = (const float*)d_in[2];
    const float* points2 = (const float*)d_in[3];
    const float* w0  = (const float*)d_in[4];
    const float* g0  = (const float*)d_in[6];
    const float* be0 = (const float*)d_in[7];
    const float* w1  = (const float*)d_in[8];
    const float* g1  = (const float*)d_in[10];
    const float* be1 = (const float*)d_in[11];
    const float* w2  = (const float*)d_in[12];
    const float* g2  = (const float*)d_in[14];
    const float* be2 = (const float*)d_in[15];
    float* out = (float*)d_out;

    __half *Wh, *Xh;
    float *Y;
    float2* affine;
    cudaGetSymbolAddress((void**)&Wh, g_Wh);
    cudaGetSymbolAddress((void**)&Xh, g_Xh);
    cudaGetSymbolAddress((void**)&Y, g_Y);
    cudaGetSymbolAddress((void**)&affine, g_affine);

    cudaFuncSetAttribute(gemm_mma, cudaFuncAttributeMaxDynamicSharedMemorySize, SMEM_TOT);

    // all weights -> fp16 in one launch
    wconv_all<<<(655360 + 255) / 256, 256>>>(w0, w1, w2);

    // geometry + interpolation + concat (fp16 [B,N,512] into g_Xh)
    transpose_p2<<<dim3(Sq / 32, 256 / 32, Bq), dim3(32, 8)>>>(points2);
    knn3_kernel<<<dim3(Nq / 128, Bq), 128>>>(xyz1, xyz2);
    interp_concat<<<dim3(Nq / 32, Bq), 256>>>(points1);

    // layer 0
    gemm_mma<<<dim3(Nq / NTt, 512 / MTt, Bq), 256, SMEM_TOT>>>(Wh, Xh, Y, 512);
    bn_fin<<<512, 256>>>(g0, be0, 0);
    act_convert<<<(Bq * Nq * Cin / 4) / 256, 256>>>(Y, affine);
    // layer 1
    gemm_mma<<<dim3(Nq / NTt, 512 / MTt, Bq), 256, SMEM_TOT>>>(Wh + 262144, Xh, Y, 512);
    bn_fin<<<512, 256>>>(g1, be1, 1);
    act_convert<<<(Bq * Nq * Cin / 4) / 256, 256>>>(Y, affine + 512);
    // layer 2
    gemm_mma<<<dim3(Nq / NTt, 256 / MTt, Bq), 256, SMEM_TOT>>>(Wh + 524288, Xh, Y, 256);
    bn_fin<<<256, 256>>>(g2, be2, 2);
    final_out<<<dim3(Nq / 32, 8, Bq), dim3(32, 8)>>>(Y, out);
}